// round 3
// baseline (speedup 1.0000x reference)
#include <cuda_runtime.h>
#include <cstdint>

// ----------------------------------------------------------------------------
// Problem constants
// ----------------------------------------------------------------------------
#define NB     32
#define CIN    128
#define HH     56
#define WW     56
#define COUT   256
#define PP     58                 // padded H/W
#define PIX    (HH*WW)            // 3136
#define NPIX   (NB*PIX)           // 100352

#define XB_SIZE (NB*PP*PP*CIN)    // 13,778,944 bytes (s8, NHWC padded)
#define WB_SIZE (9*COUT*CIN)      // 294,912 bytes

// Scratch (allocation-free rule: __device__ globals)
__device__ __align__(16) char g_x8[XB_SIZE];
__device__ __align__(16) char g_w8[WB_SIZE];
__device__ int  g_S[COUT * 9];    // border-corrected weight sums

// ----------------------------------------------------------------------------
// Helpers
// ----------------------------------------------------------------------------
__device__ __forceinline__ uint32_t smem_u32(const void* p) {
    uint32_t a;
    asm("{ .reg .u64 t; cvta.to.shared.u64 t, %1; cvt.u32.u64 %0, t; }" : "=r"(a) : "l"(p));
    return a;
}
__device__ __forceinline__ void cp16(uint32_t s, const void* g) {
    asm volatile("cp.async.cg.shared.global [%0], [%1], 16;" :: "r"(s), "l"(g));
}
#define CP_COMMIT()  asm volatile("cp.async.commit_group;" ::: "memory")
#define CP_WAIT(n)   asm volatile("cp.async.wait_group %0;" :: "n"(n) : "memory")

__device__ __forceinline__ void ldsm4(uint32_t* r, uint32_t addr) {
    asm volatile("ldmatrix.sync.aligned.m8n8.x4.shared.b16 {%0,%1,%2,%3}, [%4];"
                 : "=r"(r[0]), "=r"(r[1]), "=r"(r[2]), "=r"(r[3]) : "r"(addr));
}
__device__ __forceinline__ void imma(int* c, const uint32_t* a, uint32_t b0, uint32_t b1) {
    asm volatile("mma.sync.aligned.m16n8k32.row.col.s32.s8.s8.s32 "
                 "{%0,%1,%2,%3}, {%4,%5,%6,%7}, {%8,%9}, {%0,%1,%2,%3};"
                 : "+r"(c[0]), "+r"(c[1]), "+r"(c[2]), "+r"(c[3])
                 : "r"(a[0]), "r"(a[1]), "r"(a[2]), "r"(a[3]), "r"(b0), "r"(b1));
}

// ----------------------------------------------------------------------------
// Prep kernels
// ----------------------------------------------------------------------------
__global__ void zero_x8_kernel() {
    int i = blockIdx.x * blockDim.x + threadIdx.x;
    if (i < XB_SIZE / 16) ((uint4*)g_x8)[i] = make_uint4(0, 0, 0, 0);
}

// x NCHW int32 -> g_x8 [n][ph][pw][cin] s8 with transposed smem staging
__global__ void prep_x8_kernel(const int* __restrict__ x) {
    __shared__ int s[CIN][WW + 1];
    int n = blockIdx.x / HH, h = blockIdx.x % HH;
    int tid = threadIdx.x;
    for (int i = tid; i < CIN * WW; i += 256) {
        int c = i / WW, w = i - c * WW;
        s[c][w] = x[((n * CIN + c) * HH + h) * WW + w];
    }
    __syncthreads();
    char* dst = g_x8 + ((size_t)(n * PP + h + 1) * PP + 1) * CIN;
    for (int i = tid; i < WW * CIN; i += 256) {
        int w = i >> 7, c = i & 127;
        dst[w * CIN + c] = (char)s[c][w];
    }
}

// w OIHW int32 -> g_w8 [tap][cout][cin] s8
__global__ void prep_w8_kernel(const int* __restrict__ w) {
    int i = blockIdx.x * blockDim.x + threadIdx.x;
    if (i >= WB_SIZE) return;
    int cin = i & 127, cout = (i >> 7) & 255, tap = i >> 15;
    g_w8[i] = (char)w[(cout * CIN + cin) * 9 + tap];
}

// Border-corrected sums: S[o][rm*3+cm] = sum over valid (kh,kw) of sum_cin w
__global__ void prep_S_kernel(const int* __restrict__ w) {
    __shared__ int part[9][CIN];
    __shared__ int ws[9];
    int cout = blockIdx.x, t = threadIdx.x;  // 128 threads
    #pragma unroll
    for (int tap = 0; tap < 9; tap++)
        part[tap][t] = w[(cout * CIN + t) * 9 + tap];
    __syncthreads();
    if (t < 9) {
        int s = 0;
        for (int j = 0; j < CIN; j++) s += part[t][j];
        ws[t] = s;
    }
    __syncthreads();
    if (t == 0) {
        for (int rm = 0; rm < 3; rm++)
            for (int cm = 0; cm < 3; cm++) {
                int kh0 = (rm == 0) ? 1 : 0, kh1 = (rm == 2) ? 1 : 2;
                int kw0 = (cm == 0) ? 1 : 0, kw1 = (cm == 2) ? 1 : 2;
                int s = 0;
                for (int kh = kh0; kh <= kh1; kh++)
                    for (int kw = kw0; kw <= kw1; kw++)
                        s += ws[kh * 3 + kw];
                g_S[cout * 9 + rm * 3 + cm] = s;
            }
    }
}

// ----------------------------------------------------------------------------
// Main conv kernel
// grid (784, 2): x = pixel tile (128 px), y = cout half (128 couts)
// 256 threads, 8 warps in 2(m) x 4(n) layout; warp tile 64px x 32cout.
// K = 9 taps x 128 cin, staged per tap (A 16KB im2col, B 16KB weights),
// cp.async double buffered. SMEM rows stride 144B -> conflict-free ldmatrix.
// Output: float32 (harness carries the int8 result as float32).
// ----------------------------------------------------------------------------
#define STRIDE   144
#define TILE_B   (128 * STRIDE)          // 18432
#define OFF_A(b) ((b) * TILE_B)
#define OFF_B(b) (2 * TILE_B + (b) * TILE_B)
#define OFF_PIX  (4 * TILE_B)            // 73728: int[128]
#define OFF_BIAS (OFF_PIX + 512)         // int[128]
#define OFF_S    (OFF_BIAS + 512)        // int[128*9]
#define SMEM_TOTAL (OFF_S + 4608)        // 79360
// epilogue staging reuses [0, 67584): float tpf[128][132]
#define TPF_LD   132

__global__ void __launch_bounds__(256, 2)
conv_imma_kernel(const int* __restrict__ bias,
                 const float* __restrict__ s_in, const float* __restrict__ s_w,
                 const float* __restrict__ s_out,
                 const int* __restrict__ zpi, const int* __restrict__ zpo,
                 float* __restrict__ out) {
    extern __shared__ char smem[];
    uint32_t sb = smem_u32(smem);
    int tid = threadIdx.x;
    int wid = tid >> 5, lane = tid & 31;
    int chalf = blockIdx.y;
    int gbase = blockIdx.x * 128;

    int* pixb  = (int*)(smem + OFF_PIX);
    int* sbias = (int*)(smem + OFF_BIAS);
    int* sS    = (int*)(smem + OFF_S);

    // stage bias + border sums + pixel window bases
    if (tid < 128) {
        sbias[tid] = bias[chalf * 128 + tid];
        int g = gbase + tid;
        int n = g / PIX, p = g - n * PIX;
        int oh = p / WW, ow = p - oh * WW;
        pixb[tid] = ((n * PP + oh) * PP + ow) * CIN;
    }
    for (int i = tid; i < 128 * 9; i += 256)
        sS[i] = g_S[chalf * 128 * 9 + i];
    __syncthreads();

    // ---------------- staging helper ----------------
    auto stage = [&](int tap, int buf) {
        int kh = tap / 3, kw = tap - kh * 3;
        int tapoff = (kh * PP + kw) * CIN;
        const char* wsrc = g_w8 + tap * (COUT * CIN) + chalf * (128 * CIN);
        #pragma unroll
        for (int k = 0; k < 4; k++) {
            int i = tid + k * 256;                  // 0..1023
            int r = i >> 3, c = (i & 7) << 4;
            cp16(sb + OFF_A(buf) + r * STRIDE + c, g_x8 + pixb[r] + tapoff + c);
            cp16(sb + OFF_B(buf) + r * STRIDE + c, wsrc + r * CIN + c);
        }
    };

    int mbase = (wid & 1) * 64;     // pixel base for this warp
    int nbase = (wid >> 1) * 32;    // cout base (local) for this warp

    int acc[4][4][4];
    #pragma unroll
    for (int mt = 0; mt < 4; mt++)
        #pragma unroll
        for (int nt = 0; nt < 4; nt++)
            #pragma unroll
            for (int q = 0; q < 4; q++) acc[mt][nt][q] = 0;

    // per-lane ldmatrix address components
    uint32_t a_row = (lane & 15), a_col = (lane >> 4) << 4;
    uint32_t b_row = (lane & 7) + ((lane >> 4) & 1) * 8;
    uint32_t b_col = ((lane >> 3) & 1) << 4;

    stage(0, 0); CP_COMMIT();

    for (int tap = 0; tap < 9; tap++) {
        int buf = tap & 1;
        if (tap < 8) { stage(tap + 1, buf ^ 1); CP_COMMIT(); CP_WAIT(1); }
        else         { CP_WAIT(0); }
        __syncthreads();

        uint32_t abase = sb + OFF_A(buf);
        uint32_t bbase = sb + OFF_B(buf);
        #pragma unroll
        for (int kc = 0; kc < 4; kc++) {
            uint32_t af[4][4];
            #pragma unroll
            for (int mt = 0; mt < 4; mt++)
                ldsm4(af[mt], abase + (mbase + mt * 16 + a_row) * STRIDE + a_col + kc * 32);
            uint32_t bf[2][4];
            #pragma unroll
            for (int ntp = 0; ntp < 2; ntp++)
                ldsm4(bf[ntp], bbase + (nbase + ntp * 16 + b_row) * STRIDE + b_col + kc * 32);
            #pragma unroll
            for (int mt = 0; mt < 4; mt++)
                #pragma unroll
                for (int nt = 0; nt < 4; nt++)
                    imma(acc[mt][nt], af[mt], bf[nt >> 1][(nt & 1) * 2], bf[nt >> 1][(nt & 1) * 2 + 1]);
        }
        __syncthreads();
    }

    // ---------------- epilogue: exact zp correction + requant ----------------
    float rs = (s_in[0] * s_w[0]) / s_out[0];
    float zo = (float)zpo[0];
    int   zp = zpi[0];

    float* tpf = (float*)smem;       // reuse staging: [cout_local][px], ld=132
    #pragma unroll
    for (int mt = 0; mt < 4; mt++) {
        int row0 = mbase + mt * 16 + (lane >> 2);
        #pragma unroll
        for (int h = 0; h < 2; h++) {
            int row = row0 + h * 8;
            int g = gbase + row;
            int n = g / PIX, p = g - n * PIX;
            int oh = p / WW, ow = p - oh * WW;
            int mi = ((oh == 0) ? 0 : (oh == HH - 1) ? 6 : 3) +
                     ((ow == 0) ? 0 : (ow == WW - 1) ? 2 : 1);
            #pragma unroll
            for (int nt = 0; nt < 4; nt++) {
                int col0 = nbase + nt * 8 + 2 * (lane & 3);
                #pragma unroll
                for (int q = 0; q < 2; q++) {
                    int col = col0 + q;
                    int v = acc[mt][nt][h * 2 + q] - zp * sS[col * 9 + mi] + sbias[col];
                    float y = (float)v * rs + zo;
                    float rr = fminf(127.0f, fmaxf(-128.0f, rintf(y)));
                    tpf[col * TPF_LD + row] = rr;
                }
            }
        }
    }
    __syncthreads();

    // coalesced writeout: 128 couts x 32 groups of 4 px (PIX % 4 == 0)
    for (int i = tid; i < 4096; i += 256) {
        int row = i >> 5, grp = i & 31;
        float4 v = *(const float4*)(tpf + row * TPF_LD + grp * 4);
        int g0 = gbase + grp * 4;
        int n = g0 / PIX, p = g0 - n * PIX;
        *(float4*)(out + ((size_t)(n * COUT + chalf * 128 + row)) * PIX + p) = v;
    }
}

// ----------------------------------------------------------------------------
// Launch
// ----------------------------------------------------------------------------
extern "C" void kernel_launch(void* const* d_in, const int* in_sizes, int n_in,
                              void* d_out, int out_size) {
    (void)in_sizes; (void)n_in; (void)out_size;
    const int*   x    = (const int*)d_in[0];
    const int*   w    = (const int*)d_in[1];
    const int*   bias = (const int*)d_in[2];
    const float* si   = (const float*)d_in[3];
    const float* sw   = (const float*)d_in[4];
    const float* so   = (const float*)d_in[5];
    const int*   zpi  = (const int*)d_in[6];
    const int*   zpo  = (const int*)d_in[7];

    zero_x8_kernel<<<(XB_SIZE / 16 + 255) / 256, 256>>>();
    prep_x8_kernel<<<NB * HH, 256>>>(x);
    prep_w8_kernel<<<(WB_SIZE + 255) / 256, 256>>>(w);
    prep_S_kernel<<<COUT, 128>>>(w);

    cudaFuncSetAttribute(conv_imma_kernel,
                         cudaFuncAttributeMaxDynamicSharedMemorySize, SMEM_TOTAL);
    dim3 grid(NPIX / 128, 2);
    conv_imma_kernel<<<grid, 256, SMEM_TOTAL>>>(bias, si, sw, so, zpi, zpo, (float*)d_out);
}

// round 6
// speedup vs baseline: 1.4985x; 1.4985x over previous
#include <cuda_runtime.h>
#include <cstdint>

// ----------------------------------------------------------------------------
// Problem constants
// ----------------------------------------------------------------------------
#define NB     32
#define CIN    128
#define HH     56
#define WW     56
#define COUT   256
#define PP     58                 // padded H/W
#define PIX    (HH*WW)            // 3136
#define NPIX   (NB*PIX)           // 100352

#define XB_SIZE (NB*PP*PP*CIN)    // 13,778,944 bytes (s8, NHWC padded)
#define WB_SIZE (9*COUT*CIN)      // 294,912 bytes

// Scratch (allocation-free rule: __device__ globals)
__device__ __align__(16) char g_x8[XB_SIZE];
__device__ __align__(16) char g_w8[WB_SIZE];
__device__ int  g_S[COUT * 9];    // border-corrected weight sums

// ----------------------------------------------------------------------------
// Helpers
// ----------------------------------------------------------------------------
__device__ __forceinline__ uint32_t smem_u32(const void* p) {
    uint32_t a;
    asm("{ .reg .u64 t; cvta.to.shared.u64 t, %1; cvt.u32.u64 %0, t; }" : "=r"(a) : "l"(p));
    return a;
}
__device__ __forceinline__ void cp16(uint32_t s, const void* g) {
    asm volatile("cp.async.cg.shared.global [%0], [%1], 16;" :: "r"(s), "l"(g));
}
#define CP_COMMIT()  asm volatile("cp.async.commit_group;" ::: "memory")
#define CP_WAIT(n)   asm volatile("cp.async.wait_group %0;" :: "n"(n) : "memory")

__device__ __forceinline__ void ldsm4(uint32_t* r, uint32_t addr) {
    asm volatile("ldmatrix.sync.aligned.m8n8.x4.shared.b16 {%0,%1,%2,%3}, [%4];"
                 : "=r"(r[0]), "=r"(r[1]), "=r"(r[2]), "=r"(r[3]) : "r"(addr));
}
__device__ __forceinline__ void imma(int* c, const uint32_t* a, uint32_t b0, uint32_t b1) {
    asm volatile("mma.sync.aligned.m16n8k32.row.col.s32.s8.s8.s32 "
                 "{%0,%1,%2,%3}, {%4,%5,%6,%7}, {%8,%9}, {%0,%1,%2,%3};"
                 : "+r"(c[0]), "+r"(c[1]), "+r"(c[2]), "+r"(c[3])
                 : "r"(a[0]), "r"(a[1]), "r"(a[2]), "r"(a[3]), "r"(b0), "r"(b1));
}

// ----------------------------------------------------------------------------
// Prep kernels
// ----------------------------------------------------------------------------
__global__ void zero_x8_kernel() {
    int i = blockIdx.x * blockDim.x + threadIdx.x;
    if (i < XB_SIZE / 16) ((uint4*)g_x8)[i] = make_uint4(0, 0, 0, 0);
}

// x NCHW int32 -> g_x8 [n][ph][pw][cin] s8 with transposed smem staging
__global__ void prep_x8_kernel(const int* __restrict__ x) {
    __shared__ int s[CIN][WW + 1];
    int n = blockIdx.x / HH, h = blockIdx.x % HH;
    int tid = threadIdx.x;
    for (int i = tid; i < CIN * WW; i += 256) {
        int c = i / WW, w = i - c * WW;
        s[c][w] = x[((n * CIN + c) * HH + h) * WW + w];
    }
    __syncthreads();
    char* dst = g_x8 + ((size_t)(n * PP + h + 1) * PP + 1) * CIN;
    for (int i = tid; i < WW * CIN; i += 256) {
        int w = i >> 7, c = i & 127;
        dst[w * CIN + c] = (char)s[c][w];
    }
}

// w OIHW int32 -> g_w8 [tap][cout][cin] s8
__global__ void prep_w8_kernel(const int* __restrict__ w) {
    int i = blockIdx.x * blockDim.x + threadIdx.x;
    if (i >= WB_SIZE) return;
    int cin = i & 127, cout = (i >> 7) & 255, tap = i >> 15;
    g_w8[i] = (char)w[(cout * CIN + cin) * 9 + tap];
}

// Border-corrected sums: S[o][rm*3+cm] = sum over valid (kh,kw) of sum_cin w
__global__ void prep_S_kernel(const int* __restrict__ w) {
    __shared__ int part[9][CIN];
    __shared__ int ws[9];
    int cout = blockIdx.x, t = threadIdx.x;  // 128 threads
    #pragma unroll
    for (int tap = 0; tap < 9; tap++)
        part[tap][t] = w[(cout * CIN + t) * 9 + tap];
    __syncthreads();
    if (t < 9) {
        int s = 0;
        for (int j = 0; j < CIN; j++) s += part[t][j];
        ws[t] = s;
    }
    __syncthreads();
    if (t == 0) {
        for (int rm = 0; rm < 3; rm++)
            for (int cm = 0; cm < 3; cm++) {
                int kh0 = (rm == 0) ? 1 : 0, kh1 = (rm == 2) ? 1 : 2;
                int kw0 = (cm == 0) ? 1 : 0, kw1 = (cm == 2) ? 1 : 2;
                int s = 0;
                for (int kh = kh0; kh <= kh1; kh++)
                    for (int kw = kw0; kw <= kw1; kw++)
                        s += ws[kh * 3 + kw];
                g_S[cout * 9 + rm * 3 + cm] = s;
            }
    }
}

// ----------------------------------------------------------------------------
// Main conv kernel
// grid (784, 2): x = pixel tile (128 px), y = cout half (128 couts)
// 512 threads, 16 warps in 4(m) x 4(n) layout; warp tile 32px x 32cout.
// K = 9 taps x 128 cin, staged per tap (A 16KB im2col, B 16KB weights),
// cp.async double buffered. SMEM rows stride 144B -> conflict-free ldmatrix.
// Output: float32 (harness carries the int8 result as float32).
// ----------------------------------------------------------------------------
#define STRIDE   144
#define TILE_B   (128 * STRIDE)          // 18432
#define OFF_A(b) ((b) * TILE_B)
#define OFF_B(b) (2 * TILE_B + (b) * TILE_B)
#define OFF_PIX  (4 * TILE_B)            // 73728: int[128]
#define OFF_BIAS (OFF_PIX + 512)         // int[128]
#define OFF_S    (OFF_BIAS + 512)        // int[128*9]
#define SMEM_TOTAL (OFF_S + 4608)        // 79360
// epilogue staging reuses [0, 67584): float tpf[128][132]
#define TPF_LD   132

__global__ void __launch_bounds__(512, 1)
conv_imma_kernel(const int* __restrict__ bias,
                 const float* __restrict__ s_in, const float* __restrict__ s_w,
                 const float* __restrict__ s_out,
                 const int* __restrict__ zpi, const int* __restrict__ zpo,
                 float* __restrict__ out) {
    extern __shared__ char smem[];
    uint32_t sb = smem_u32(smem);
    int tid = threadIdx.x;
    int wid = tid >> 5, lane = tid & 31;
    int chalf = blockIdx.y;
    int gbase = blockIdx.x * 128;

    int* pixb  = (int*)(smem + OFF_PIX);
    int* sbias = (int*)(smem + OFF_BIAS);
    int* sS    = (int*)(smem + OFF_S);

    // stage bias + border sums + pixel window bases
    if (tid < 128) {
        sbias[tid] = bias[chalf * 128 + tid];
        int g = gbase + tid;
        int n = g / PIX, p = g - n * PIX;
        int oh = p / WW, ow = p - oh * WW;
        pixb[tid] = ((n * PP + oh) * PP + ow) * CIN;
    }
    for (int i = tid; i < 128 * 9; i += 512)
        sS[i] = g_S[chalf * 128 * 9 + i];
    __syncthreads();

    // ---------------- staging helper ----------------
    auto stage = [&](int tap, int buf) {
        int kh = tap / 3, kw = tap - kh * 3;
        int tapoff = (kh * PP + kw) * CIN;
        const char* wsrc = g_w8 + tap * (COUT * CIN) + chalf * (128 * CIN);
        #pragma unroll
        for (int k = 0; k < 2; k++) {
            int i = tid + k * 512;                  // 0..1023
            int r = i >> 3, c = (i & 7) << 4;
            cp16(sb + OFF_A(buf) + r * STRIDE + c, g_x8 + pixb[r] + tapoff + c);
            cp16(sb + OFF_B(buf) + r * STRIDE + c, wsrc + r * CIN + c);
        }
    };

    int mbase = (wid & 3) * 32;     // pixel base for this warp
    int nbase = (wid >> 2) * 32;    // cout base (local) for this warp

    int acc[2][4][4];
    #pragma unroll
    for (int mt = 0; mt < 2; mt++)
        #pragma unroll
        for (int nt = 0; nt < 4; nt++)
            #pragma unroll
            for (int q = 0; q < 4; q++) acc[mt][nt][q] = 0;

    // per-lane ldmatrix address components
    uint32_t a_row = (lane & 15), a_col = (lane >> 4) << 4;
    uint32_t b_row = (lane & 7) + ((lane >> 4) & 1) * 8;
    uint32_t b_col = ((lane >> 3) & 1) << 4;

    stage(0, 0); CP_COMMIT();

    for (int tap = 0; tap < 9; tap++) {
        int buf = tap & 1;
        if (tap < 8) { stage(tap + 1, buf ^ 1); CP_COMMIT(); CP_WAIT(1); }
        else         { CP_WAIT(0); }
        __syncthreads();

        uint32_t abase = sb + OFF_A(buf);
        uint32_t bbase = sb + OFF_B(buf);
        #pragma unroll
        for (int kc = 0; kc < 4; kc++) {
            uint32_t bf[2][4];
            #pragma unroll
            for (int ntp = 0; ntp < 2; ntp++)
                ldsm4(bf[ntp], bbase + (nbase + ntp * 16 + b_row) * STRIDE + b_col + kc * 32);
            #pragma unroll
            for (int mt = 0; mt < 2; mt++) {
                uint32_t af[4];
                ldsm4(af, abase + (mbase + mt * 16 + a_row) * STRIDE + a_col + kc * 32);
                #pragma unroll
                for (int nt = 0; nt < 4; nt++)
                    imma(acc[mt][nt], af, bf[nt >> 1][(nt & 1) * 2], bf[nt >> 1][(nt & 1) * 2 + 1]);
            }
        }
        __syncthreads();
    }

    // ---------------- epilogue: exact zp correction + requant ----------------
    float rs = (s_in[0] * s_w[0]) / s_out[0];
    float zo = (float)zpo[0];
    int   zp = zpi[0];

    float* tpf = (float*)smem;       // reuse staging: [cout_local][px], ld=132
    #pragma unroll
    for (int mt = 0; mt < 2; mt++) {
        int row0 = mbase + mt * 16 + (lane >> 2);
        #pragma unroll
        for (int h = 0; h < 2; h++) {
            int row = row0 + h * 8;
            int g = gbase + row;
            int n = g / PIX, p = g - n * PIX;
            int oh = p / WW, ow = p - oh * WW;
            int mi = ((oh == 0) ? 0 : (oh == HH - 1) ? 6 : 3) +
                     ((ow == 0) ? 0 : (ow == WW - 1) ? 2 : 1);
            #pragma unroll
            for (int nt = 0; nt < 4; nt++) {
                int col0 = nbase + nt * 8 + 2 * (lane & 3);
                #pragma unroll
                for (int q = 0; q < 2; q++) {
                    int col = col0 + q;
                    int v = acc[mt][nt][h * 2 + q] - zp * sS[col * 9 + mi] + sbias[col];
                    float y = (float)v * rs + zo;
                    float rr = fminf(127.0f, fmaxf(-128.0f, rintf(y)));
                    tpf[col * TPF_LD + row] = rr;
                }
            }
        }
    }
    __syncthreads();

    // coalesced writeout: 128 couts x 32 groups of 4 px (PIX % 4 == 0)
    for (int i = tid; i < 4096; i += 512) {
        int row = i >> 5, grp = i & 31;
        float4 v = *(const float4*)(tpf + row * TPF_LD + grp * 4);
        int g0 = gbase + grp * 4;
        int n = g0 / PIX, p = g0 - n * PIX;
        *(float4*)(out + ((size_t)(n * COUT + chalf * 128 + row)) * PIX + p) = v;
    }
}

// ----------------------------------------------------------------------------
// Launch
// ----------------------------------------------------------------------------
extern "C" void kernel_launch(void* const* d_in, const int* in_sizes, int n_in,
                              void* d_out, int out_size) {
    (void)in_sizes; (void)n_in; (void)out_size;
    const int*   x    = (const int*)d_in[0];
    const int*   w    = (const int*)d_in[1];
    const int*   bias = (const int*)d_in[2];
    const float* si   = (const float*)d_in[3];
    const float* sw   = (const float*)d_in[4];
    const float* so   = (const float*)d_in[5];
    const int*   zpi  = (const int*)d_in[6];
    const int*   zpo  = (const int*)d_in[7];

    zero_x8_kernel<<<(XB_SIZE / 16 + 255) / 256, 256>>>();
    prep_x8_kernel<<<NB * HH, 256>>>(x);
    prep_w8_kernel<<<(WB_SIZE + 255) / 256, 256>>>(w);
    prep_S_kernel<<<COUT, 128>>>(w);

    cudaFuncSetAttribute(conv_imma_kernel,
                         cudaFuncAttributeMaxDynamicSharedMemorySize, SMEM_TOTAL);
    dim3 grid(NPIX / 128, 2);
    conv_imma_kernel<<<grid, 512, SMEM_TOTAL>>>(bias, si, sw, so, zpi, zpo, (float*)d_out);
}